// round 17
// baseline (speedup 1.0000x reference)
#include <cuda_runtime.h>
#include <cuda_bf16.h>
#include <math.h>

#define B_    64
#define T_    512
#define E_    512
#define H_    1024
#define V_    32000
#define G4_   4096   /* 4*H */
#define TCH_  128    /* time chunk (xproj scratch + persistent span) */
#define NBLK_ 128    /* persistent grid */
#define UPB_  8      /* hidden units per block */

// ---- global scratch (alloc-free rule: __device__ globals) ----
__device__ float g_xproj[(size_t)B_ * TCH_ * G4_];     // 128 MB chunk slab
__device__ __nv_bfloat16 g_emb_hi[(size_t)V_ * E_];    // bf16 emb table hi
__device__ __nv_bfloat16 g_emb_lo[(size_t)V_ * E_];    // bf16 emb table lo
__device__ __nv_bfloat16 g_wt_hi[(size_t)G4_ * E_];    // W_ih^T bf16 hi [N][K]
__device__ __nv_bfloat16 g_wt_lo[(size_t)G4_ * E_];    // W_ih^T bf16 lo
__device__ __nv_bfloat16 g_hbf_hi[2][B_ * H_];         // h bf16 hi, [B][H]
__device__ __nv_bfloat16 g_hbf_lo[2][B_ * H_];         // h bf16 lo
__device__ float g_hfin[B_ * H_];                      // final h fp32 [B][H]
__device__ float g_cst[B_ * H_];                       // c state [B][H]
__device__ unsigned g_bar[T_];                         // per-step arrivals

// ---------------- helpers ---------------------------------------------------
__device__ __forceinline__ float tanha(float x) {
    float y;
    asm("tanh.approx.f32 %0, %1;" : "=f"(y) : "f"(x));
    return y;
}
__device__ __forceinline__ float sigm(float x) {
    return __fdividef(1.f, 1.f + __expf(-x));
}
__device__ __forceinline__ unsigned pkbf_hi(float a, float b) {
    unsigned short x = __bfloat16_as_ushort(__float2bfloat16(a));
    unsigned short y = __bfloat16_as_ushort(__float2bfloat16(b));
    return (unsigned)x | ((unsigned)y << 16);
}

// mma.sync m16n8k16 bf16 (base sm_80+ instruction)
__device__ __forceinline__ void mma16816(float& c0, float& c1, float& c2, float& c3,
                                         unsigned a0, unsigned a1, unsigned a2,
                                         unsigned a3, unsigned b0, unsigned b1) {
    asm volatile(
        "mma.sync.aligned.m16n8k16.row.col.f32.bf16.bf16.f32 "
        "{%0,%1,%2,%3},{%4,%5,%6,%7},{%8,%9},{%0,%1,%2,%3};"
        : "+f"(c0), "+f"(c1), "+f"(c2), "+f"(c3)
        : "r"(a0), "r"(a1), "r"(a2), "r"(a3), "r"(b0), "r"(b1));
}

// ---------------------------- init ------------------------------------------
__global__ void init_state() {
    int i = blockIdx.x * blockDim.x + threadIdx.x;
    if (i < B_ * H_) {
        g_hbf_hi[0][i] = __ushort_as_bfloat16(0);
        g_hbf_lo[0][i] = __ushort_as_bfloat16(0);
        g_cst[i] = 0.f;
    }
    if (i < T_) g_bar[i] = 0u;
}

// ---------------- prep: bf16 hi/lo tables (once per run) --------------------
__global__ void prep_bf16(const float* __restrict__ emb,
                          const float* __restrict__ Wih) {
    int i = blockIdx.x * blockDim.x + threadIdx.x;
    if (i < V_ * E_) {
        float v = emb[i];
        __nv_bfloat16 h = __float2bfloat16(v);
        g_emb_hi[i] = h;
        g_emb_lo[i] = __float2bfloat16(v - __bfloat162float(h));
    }
    if (i < E_ * G4_) {
        int k = i >> 12, n = i & 4095;
        float v = Wih[i];
        __nv_bfloat16 h = __float2bfloat16(v);
        g_wt_hi[(size_t)n * E_ + k] = h;
        g_wt_lo[(size_t)n * E_ + k] = __float2bfloat16(v - __bfloat162float(h));
    }
}

// ---------------- Phase 1: HMMA Xproj chunk (unchanged) ---------------------
__global__ __launch_bounds__(256) void xproj_hmma(const int* __restrict__ src,
                                                  const float* __restrict__ bias,
                                                  int t0) {
    __shared__ __align__(16) __nv_bfloat16 Ah[128][40], Al[128][40];
    __shared__ __align__(16) __nv_bfloat16 Bh[64][40],  Bl[64][40];
    __shared__ int srow[128];

    const int tid = threadIdx.x;
    const int wid = tid >> 5, lane = tid & 31;
    const int m0 = blockIdx.y * 128;
    const int n0 = blockIdx.x * 64;
    const int wm = wid >> 1, wn = wid & 1;

    if (tid < 128) {
        int m = m0 + tid;
        srow[tid] = src[(m & 63) * T_ + t0 + (m >> 6)];
    }

    float acc[2][4][4];
    #pragma unroll
    for (int a = 0; a < 2; a++)
        #pragma unroll
        for (int b = 0; b < 4; b++)
            #pragma unroll
            for (int c = 0; c < 4; c++) acc[a][b][c] = 0.f;

    for (int ch = 0; ch < 16; ch++) {
        const int k0 = ch * 32;
        __syncthreads();
        #pragma unroll
        for (int i = 0; i < 2; i++) {
            int idx = tid + i * 256;
            int r = idx >> 2, q = idx & 3;
            const size_t go = (size_t)srow[r] * E_ + k0 + q * 8;
            *reinterpret_cast<uint4*>(&Ah[r][q * 8]) =
                *reinterpret_cast<const uint4*>(&g_emb_hi[go]);
            *reinterpret_cast<uint4*>(&Al[r][q * 8]) =
                *reinterpret_cast<const uint4*>(&g_emb_lo[go]);
        }
        {
            int r = tid >> 2, q = tid & 3;
            const size_t go = (size_t)(n0 + r) * E_ + k0 + q * 8;
            *reinterpret_cast<uint4*>(&Bh[r][q * 8]) =
                *reinterpret_cast<const uint4*>(&g_wt_hi[go]);
            *reinterpret_cast<uint4*>(&Bl[r][q * 8]) =
                *reinterpret_cast<const uint4*>(&g_wt_lo[go]);
        }
        __syncthreads();

        #pragma unroll
        for (int ks = 0; ks < 2; ks++) {
            const int kc = ks * 16 + (lane & 3) * 2;
            unsigned ah[2][4], al[2][4];
            #pragma unroll
            for (int mf = 0; mf < 2; mf++) {
                int rm = wm * 32 + mf * 16 + (lane >> 2);
                ah[mf][0] = *reinterpret_cast<const unsigned*>(&Ah[rm][kc]);
                ah[mf][1] = *reinterpret_cast<const unsigned*>(&Ah[rm + 8][kc]);
                ah[mf][2] = *reinterpret_cast<const unsigned*>(&Ah[rm][kc + 8]);
                ah[mf][3] = *reinterpret_cast<const unsigned*>(&Ah[rm + 8][kc + 8]);
                al[mf][0] = *reinterpret_cast<const unsigned*>(&Al[rm][kc]);
                al[mf][1] = *reinterpret_cast<const unsigned*>(&Al[rm + 8][kc]);
                al[mf][2] = *reinterpret_cast<const unsigned*>(&Al[rm][kc + 8]);
                al[mf][3] = *reinterpret_cast<const unsigned*>(&Al[rm + 8][kc + 8]);
            }
            #pragma unroll
            for (int nf = 0; nf < 4; nf++) {
                int cn = wn * 32 + nf * 8 + (lane >> 2);
                unsigned bh0 = *reinterpret_cast<const unsigned*>(&Bh[cn][kc]);
                unsigned bh1 = *reinterpret_cast<const unsigned*>(&Bh[cn][kc + 8]);
                unsigned bl0 = *reinterpret_cast<const unsigned*>(&Bl[cn][kc]);
                unsigned bl1 = *reinterpret_cast<const unsigned*>(&Bl[cn][kc + 8]);
                #pragma unroll
                for (int mf = 0; mf < 2; mf++) {
                    mma16816(acc[mf][nf][0], acc[mf][nf][1],
                             acc[mf][nf][2], acc[mf][nf][3],
                             ah[mf][0], ah[mf][1], ah[mf][2], ah[mf][3],
                             bh0, bh1);
                    mma16816(acc[mf][nf][0], acc[mf][nf][1],
                             acc[mf][nf][2], acc[mf][nf][3],
                             al[mf][0], al[mf][1], al[mf][2], al[mf][3],
                             bh0, bh1);
                    mma16816(acc[mf][nf][0], acc[mf][nf][1],
                             acc[mf][nf][2], acc[mf][nf][3],
                             ah[mf][0], ah[mf][1], ah[mf][2], ah[mf][3],
                             bl0, bl1);
                }
            }
        }
    }

    #pragma unroll
    for (int nf = 0; nf < 4; nf++) {
        int n = n0 + wn * 32 + nf * 8 + (lane & 3) * 2;
        float2 bv = *reinterpret_cast<const float2*>(&bias[n]);
        #pragma unroll
        for (int mf = 0; mf < 2; mf++) {
            int m = m0 + wm * 32 + mf * 16 + (lane >> 2);
            *reinterpret_cast<float2*>(&g_xproj[(size_t)m * G4_ + n]) =
                make_float2(acc[mf][nf][0] + bv.x, acc[mf][nf][1] + bv.y);
            *reinterpret_cast<float2*>(&g_xproj[(size_t)(m + 8) * G4_ + n]) =
                make_float2(acc[mf][nf][2] + bv.x, acc[mf][nf][3] + bv.y);
        }
    }
}

// ---------------- Phase 2: persistent HMMA LSTM, 128-k chunks ---------------
// 128 blocks x 512 threads (16 warps). Warp w: mt = w>>2 (16 batches),
// kq = w&3 (32-k slice within each staged 128-k chunk = 2 sub-slices of 16 k).
// 8 chunks/step, double-buffered, 1 sync/chunk, 24 MMAs/warp/chunk.
// Partials zs[4][64][33] OVERLAY hbuf[0] (safe: buf0's last MMA read is
// chunk 6, guarded by the chunk-6/7 syncs; next step's staging of buf0 is
// ordered behind the reduce by the grid barrier's syncthreads).
//
// SMEM map (dynamic, 208896 B):
//   [0,      65536)   Whi frags: [nf][gk(64)][lane][2 u32]
//   [65536, 131072)   Wlo frags
//   [131072,200704)   hbuf: 2 x { hi[64][136]bf16 (17408B) + lo same } = 69632
//                     zs[4][64][33] f32 (33792B) overlays hbuf[0]
//   [200704,208896)   xs[64][32] f32 (Xproj slab)
#define SMEM_BYTES_ 208896

__global__ __launch_bounds__(512, 1) void lstm_chunk(const float* __restrict__ Whh,
                                                     int s0) {
    extern __shared__ __align__(16) char smem[];
    float* zs = (float*)(smem + 131072);        // overlays hbuf[0]
    float* xs = (float*)(smem + 200704);

    const int tid  = threadIdx.x;
    const int wid  = tid >> 5;
    const int lane = tid & 31;
    const int u0   = blockIdx.x * UPB_;
    const int mt   = wid >> 2;                  // m-tile (16 batches)
    const int kq   = wid & 3;                   // 32-k slice within chunk
    const int ln3  = lane & 3;
    const int rm0  = mt * 16 + (lane >> 2);     // A-frag row (batch)

    // ---- convert W slice into fragment-ordered smem (once per launch) ----
    #pragma unroll
    for (int it = 0; it < 16; it++) {
        int slot = it * 512 + tid;
        int ln = slot & 31, gk = (slot >> 5) & 63, ntc = slot >> 11;
        int c = ntc * 8 + (ln >> 2);
        int kb = gk * 16 + (ln & 3) * 2;
        const float* wp = Whh + (size_t)kb * G4_ + (c >> 3) * H_ + u0 + (c & 7);
        float w0 = wp[0], w1 = wp[G4_];
        float w8 = wp[(size_t)8 * G4_], w9 = wp[(size_t)9 * G4_];
        float h0 = __bfloat162float(__float2bfloat16(w0));
        float h1 = __bfloat162float(__float2bfloat16(w1));
        float h8 = __bfloat162float(__float2bfloat16(w8));
        float h9 = __bfloat162float(__float2bfloat16(w9));
        unsigned off = (unsigned)(ntc * 64 + gk) * 256 + ln * 8;
        *reinterpret_cast<uint2*>(smem + off) =
            make_uint2(pkbf_hi(w0, w1), pkbf_hi(w8, w9));
        *reinterpret_cast<uint2*>(smem + 65536 + off) =
            make_uint2(pkbf_hi(w0 - h0, w1 - h1), pkbf_hi(w8 - h8, w9 - h9));
    }
    // ---- c state in registers: thread owns cell (b = tid>>3, j = tid&7) ----
    const int gb = tid >> 3, gj = tid & 7;
    float creg = g_cst[gb * H_ + u0 + gj];
    __syncthreads();

    // staging map: thread stages hi+lo 2x8-k groups: b = tid>>3, k8 = tid&7
    const int sb = tid >> 3, sk8 = tid & 7;
    const int so = sb * 272 + sk8 * 16;         // byte offset within hi region

    for (int ls = 0; ls < TCH_; ls++) {
        const int s = s0 + ls;
        const __nv_bfloat16* hbi = g_hbf_hi[s & 1];
        const __nv_bfloat16* hlo = g_hbf_lo[s & 1];
        __nv_bfloat16* nhi = g_hbf_hi[(s + 1) & 1];
        __nv_bfloat16* nlo = g_hbf_lo[(s + 1) & 1];
        const float* __restrict__ Xp = g_xproj + (size_t)ls * (B_ * G4_);

        // ---- Xproj slab prefetch into xs (consumed at step end) ----
        {
            int seg = tid >> 1, o = (tid & 1) * 4;
            int b = seg >> 2, g = seg & 3;
            float4 xv = __ldg(reinterpret_cast<const float4*>(
                &Xp[(size_t)b * G4_ + g * H_ + u0 + o]));
            *reinterpret_cast<float4*>(&xs[b * 32 + g * 8 + o]) = xv;
        }

        float acc[4][4];
        #pragma unroll
        for (int a = 0; a < 4; a++)
            #pragma unroll
            for (int c = 0; c < 4; c++) acc[a][c] = 0.f;

        // ---- stage chunk 0 into buf0, prefetch chunk 1 ----
        uint4 ph0 = __ldcg(reinterpret_cast<const uint4*>(&hbi[sb * H_ + sk8 * 8]));
        uint4 ph1 = __ldcg(reinterpret_cast<const uint4*>(&hbi[sb * H_ + 64 + sk8 * 8]));
        uint4 pl0 = __ldcg(reinterpret_cast<const uint4*>(&hlo[sb * H_ + sk8 * 8]));
        uint4 pl1 = __ldcg(reinterpret_cast<const uint4*>(&hlo[sb * H_ + 64 + sk8 * 8]));
        {
            char* b0 = smem + 131072;
            *reinterpret_cast<uint4*>(b0 + so) = ph0;
            *reinterpret_cast<uint4*>(b0 + so + 128) = ph1;
            *reinterpret_cast<uint4*>(b0 + 17408 + so) = pl0;
            *reinterpret_cast<uint4*>(b0 + 17408 + so + 128) = pl1;
        }
        ph0 = __ldcg(reinterpret_cast<const uint4*>(&hbi[sb * H_ + 128 + sk8 * 8]));
        ph1 = __ldcg(reinterpret_cast<const uint4*>(&hbi[sb * H_ + 192 + sk8 * 8]));
        pl0 = __ldcg(reinterpret_cast<const uint4*>(&hlo[sb * H_ + 128 + sk8 * 8]));
        pl1 = __ldcg(reinterpret_cast<const uint4*>(&hlo[sb * H_ + 192 + sk8 * 8]));
        __syncthreads();

        for (int ch = 0; ch < 8; ch++) {
            if (ch < 7) {
                char* nb = smem + 131072 + ((ch + 1) & 1) * 34816;
                *reinterpret_cast<uint4*>(nb + so) = ph0;
                *reinterpret_cast<uint4*>(nb + so + 128) = ph1;
                *reinterpret_cast<uint4*>(nb + 17408 + so) = pl0;
                *reinterpret_cast<uint4*>(nb + 17408 + so + 128) = pl1;
            }
            if (ch < 6) {
                int kb = (ch + 2) * 128;
                ph0 = __ldcg(reinterpret_cast<const uint4*>(&hbi[sb * H_ + kb + sk8 * 8]));
                ph1 = __ldcg(reinterpret_cast<const uint4*>(&hbi[sb * H_ + kb + 64 + sk8 * 8]));
                pl0 = __ldcg(reinterpret_cast<const uint4*>(&hlo[sb * H_ + kb + sk8 * 8]));
                pl1 = __ldcg(reinterpret_cast<const uint4*>(&hlo[sb * H_ + kb + 64 + sk8 * 8]));
            }
            const char* cb = smem + 131072 + (ch & 1) * 34816;
            const unsigned* Hh = (const unsigned*)cb;
            const unsigned* Hl = (const unsigned*)(cb + 17408);
            #pragma unroll
            for (int t = 0; t < 2; t++) {
                const int wbase = rm0 * 68 + kq * 16 + t * 8 + ln3;
                unsigned ah0 = Hh[wbase],       ah1 = Hh[wbase + 544];
                unsigned ah2 = Hh[wbase + 4],   ah3 = Hh[wbase + 548];
                unsigned al0 = Hl[wbase],       al1 = Hl[wbase + 544];
                unsigned al2 = Hl[wbase + 4],   al3 = Hl[wbase + 548];
                const int gk = ch * 8 + kq * 2 + t;
                #pragma unroll
                for (int nf = 0; nf < 4; nf++) {
                    uint2 bh = *reinterpret_cast<const uint2*>(
                        smem + (unsigned)(nf * 64 + gk) * 256 + lane * 8);
                    uint2 bl = *reinterpret_cast<const uint2*>(
                        smem + 65536 + (unsigned)(nf * 64 + gk) * 256 + lane * 8);
                    mma16816(acc[nf][0], acc[nf][1], acc[nf][2], acc[nf][3],
                             ah0, ah1, ah2, ah3, bh.x, bh.y);
                    mma16816(acc[nf][0], acc[nf][1], acc[nf][2], acc[nf][3],
                             al0, al1, al2, al3, bh.x, bh.y);
                    mma16816(acc[nf][0], acc[nf][1], acc[nf][2], acc[nf][3],
                             ah0, ah1, ah2, ah3, bl.x, bl.y);
                }
            }
            __syncthreads();
        }

        // ---- write k-slice partials (zs overlays buf0; safe, see header) ----
        #pragma unroll
        for (int nf = 0; nf < 4; nf++) {
            int rz = mt * 16 + (lane >> 2);
            int cz = nf * 8 + ln3 * 2;
            float* zp = zs + kq * 2112 + rz * 33 + cz;
            zp[0] = acc[nf][0];
            zp[1] = acc[nf][1];
            zp[264] = acc[nf][2];           // (rz+8)*33
            zp[265] = acc[nf][3];
        }
        __syncthreads();

        // ---- reduce 4 kq partials + Xproj; gates; one cell per thread ----
        {
            float z[4];
            #pragma unroll
            for (int g = 0; g < 4; g++) {
                int e = gb * 33 + g * 8 + gj;
                z[g] = xs[gb * 32 + g * 8 + gj]
                     + zs[e] + zs[2112 + e] + zs[4224 + e] + zs[6336 + e];
            }
            float ig = sigm(z[0]);
            float fg = sigm(z[1]);
            float gg = tanha(z[2]);
            float og = sigm(z[3]);
            float cn = fg * creg + ig * gg;
            creg = cn;
            float h = og * tanha(cn);
            __nv_bfloat16 bh = __float2bfloat16(h);
            nhi[gb * H_ + u0 + gj] = bh;
            nlo[gb * H_ + u0 + gj] = __float2bfloat16(h - __bfloat162float(bh));
            if (s == T_ - 1) g_hfin[gb * H_ + u0 + gj] = h;
        }

        // ---- grid-wide barrier (release arrival, acquire spin) ----
        __threadfence();
        __syncthreads();
        if (tid == 0) {
            asm volatile("red.release.gpu.global.add.u32 [%0], 1;"
                         :: "l"(&g_bar[s]) : "memory");
            unsigned v;
            do {
                asm volatile("ld.acquire.gpu.global.u32 %0, [%1];"
                             : "=r"(v) : "l"(&g_bar[s]) : "memory");
            } while (v < NBLK_);
        }
        __syncthreads();
    }

    // ---- persist c state ----
    g_cst[gb * H_ + u0 + gj] = creg;
}

// ------------------------------- output -------------------------------------
__global__ void write_out(float* __restrict__ out) {
    int i = blockIdx.x * blockDim.x + threadIdx.x;
    if (i < B_ * H_) {
        out[i] = g_hfin[i];
        out[B_ * H_ + i] = g_cst[i];
    }
}

extern "C" void kernel_launch(void* const* d_in, const int* in_sizes, int n_in,
                              void* d_out, int out_size) {
    (void)in_sizes; (void)n_in; (void)out_size;
    const int*   src  = (const int*)d_in[0];
    const float* emb  = (const float*)d_in[1];
    const float* Wih  = (const float*)d_in[2];
    const float* Whh  = (const float*)d_in[3];
    const float* bias = (const float*)d_in[4];
    float* out = (float*)d_out;

    cudaFuncSetAttribute(lstm_chunk, cudaFuncAttributeMaxDynamicSharedMemorySize,
                         SMEM_BYTES_);

    // Launch order keeps lstm_chunk at launch #6 for ncu's "-s 5 -c 1".
    init_state<<<(B_ * H_ + 255) / 256, 256>>>();
    prep_bf16<<<(V_ * E_ + 255) / 256, 256>>>(emb, Wih);
    for (int t0 = 0; t0 < T_; t0 += TCH_) {
        xproj_hmma<<<dim3(G4_ / 64, (TCH_ * B_) / 128), 256>>>(src, bias, t0);
        lstm_chunk<<<NBLK_, 512, SMEM_BYTES_>>>(Whh, t0);
    }
    write_out<<<(B_ * H_ + 255) / 256, 256>>>(out);
}